// round 16
// baseline (speedup 1.0000x reference)
#include <cuda_runtime.h>
#include <math.h>

#define IMG 256
#define MAX_R 64
#define N_AG 2047
#define N_ENT 4095
#define FOVH 0.7853981633974483f   /* pi/4 = FOV/2 */
#define PT 1024
#define NB 128                     /* 2 cols per block, single wave */

/* fixed-slot records: {pxi<<16 | pr*pr, depth_bits}; invalid => pxi=-30000 */
__device__ uint2 g_rec[4096];
__device__ int   g_done  = 0;      /* producer arrivals  (reset each run) */
__device__ int   g_done2 = 0;      /* reset-phase arrivals */

__global__ __launch_bounds__(PT)
void render_kernel(const float* __restrict__ agent,
                   const float* __restrict__ goal,
                   const float* __restrict__ others,
                   const float* __restrict__ obs,
                   float* __restrict__ out) {
    __shared__ uint2 s_rec0[2048];     /* col c0: {rem = pr2-dx2, depth} */
    __shared__ uint2 s_rec1[2048];     /* col c1 */
    __shared__ int   s_wcnt[32];
    __shared__ int   s_wbase[33];      /* packed cnt0<<16 | cnt1 */

    int tid  = threadIdx.x;
    int warp = tid >> 5;
    unsigned lane = tid & 31;
    int c0 = blockIdx.x * 2;

    /* ---- producer: warp 0 transforms 32 entities (grid total = 4096) ---- */
    if (warp == 0) {
        int e = blockIdx.x * 32 + (int)lane;

        float ax = agent[0], ay = agent[1];
        float vx = goal[0] - ax, vy = goal[1] - ay;
        float inv = 1.0f / (sqrtf(vx * vx + vy * vy) + 1e-8f);
        vx *= inv; vy *= inv;
        float cb = vy, sb = vx;

        uint2 rec = make_uint2(((unsigned)(-30000)) << 16, 0x3F800000u);
        if (e < N_ENT) {
            float ex, ey, r, h;
            if (e < N_AG) {
                float2 p = __ldg((const float2*)(others + 2 * e));
                ex = p.x; ey = p.y; r = 0.05f; h = 0.2f;
            } else {
                int o = e - N_AG;
                ex = __ldg(obs + 3 * o);
                ey = __ldg(obs + 3 * o + 1);
                r  = __ldg(obs + 3 * o + 2);
                h  = 0.5f;
            }
            float rx = ex - ax, ry = ey - ay;
            float camx =  cb * rx + sb * ry;
            float camy = -sb * rx + cb * ry;
            float dist = sqrtf(camx * camx + camy * camy);
            float angle = atan2f(camx, camy);

            if ((camy >= 0.0f) && (dist <= 3.0f) && (fabsf(angle) <= FOVH)) {
                float pixel_x = angle / FOVH * 0.5f;
                int pxi = (int)floorf((pixel_x + 0.5f) * (float)IMG);
                int pr  = (int)floorf(r / (dist + 1e-8f) * (float)IMG * 0.5f);
                pr = min(max(pr, 1), MAX_R);
                float depth = fminf(dist / 3.0f, 1.0f) * (1.0f - h * 0.3f);
                depth = fmaxf(depth, 0.0f);
                rec.x = ((unsigned)pxi << 16) | (unsigned)(pr * pr);
                rec.y = __float_as_uint(depth);
            }
        }
        g_rec[e] = rec;
        __threadfence();
        __syncwarp();
        if (lane == 0) atomicAdd(&g_done, 1);
    }

    /* ---- spinner: one thread waits for all 128 producer arrivals ---- */
    if (tid == 32) {
        while (atomicAdd(&g_done, 0) < NB) { }
        __threadfence();
    }

    /* ---- background rows meanwhile (rows 0..63, 193..255, 2 cols) ---- */
    if (tid >= 64 && tid < 318) {
        int t = tid - 64;
        int r = t >> 1;
        int row = (r < 64) ? r : r + 129;
        out[row * IMG + c0 + (t & 1)] = 1.0f;
    }
    __syncthreads();                   /* records globally visible past here */

    /* self-reset (proven): 128th post-spin arriver zeroes both counters */
    if (tid == 0) {
        int d = atomicAdd(&g_done2, 1);
        if (d == NB - 1) { g_done = 0; g_done2 = 0; }
    }

    /* ---- phase A: 4 slots/thread, hit-test both columns, ballots ---- */
    int rem0[4], rem1[4]; unsigned dep[4], m0[4], m1[4];
    int cnt0 = 0, cnt1 = 0;
    #pragma unroll
    for (int k = 0; k < 4; k++) {
        uint2 g = __ldcg(&g_rec[tid + k * PT]);
        int pxi = (int)g.x >> 16;
        int pr2 = (int)(g.x & 0xffffu);
        int dx0 = c0 - pxi;
        int dx1 = dx0 + 1;
        rem0[k] = pr2 - dx0 * dx0;
        rem1[k] = pr2 - dx1 * dx1;
        dep[k]  = g.y;
        m0[k] = __ballot_sync(0xffffffffu, rem0[k] >= 0);
        m1[k] = __ballot_sync(0xffffffffu, rem1[k] >= 0);
        cnt0 += __popc(m0[k]);
        cnt1 += __popc(m1[k]);
    }
    if (lane == 0) s_wcnt[warp] = (cnt0 << 16) | cnt1;
    __syncthreads();

    if (warp == 0) {                   /* packed exclusive scan (no carry) */
        int v = s_wcnt[lane];
        int incl = v;
        #pragma unroll
        for (int off = 1; off < 32; off <<= 1) {
            int t = __shfl_up_sync(0xffffffffu, incl, off);
            if ((int)lane >= off) incl += t;
        }
        s_wbase[lane] = incl - v;
        if (lane == 31) s_wbase[32] = incl;
    }
    __syncthreads();

    int b0 = s_wbase[warp] >> 16;
    int b1 = s_wbase[warp] & 0xffff;
    unsigned pre = (1u << lane) - 1u;
    #pragma unroll
    for (int k = 0; k < 4; k++) {
        if (rem0[k] >= 0)
            s_rec0[b0 + __popc(m0[k] & pre)] = make_uint2((unsigned)rem0[k], dep[k]);
        if (rem1[k] >= 0)
            s_rec1[b1 + __popc(m1[k] & pre)] = make_uint2((unsigned)rem1[k], dep[k]);
        b0 += __popc(m0[k]);
        b1 += __popc(m1[k]);
    }
    __syncthreads();
    int nc0 = s_wbase[32] >> 16;
    int nc1 = s_wbase[32] & 0xffff;

    /* ---- phase B: tid = [dyidx:6][colsel:1][oct:3]; dy in 1..64.
       Symmetry: out[128+dy] == out[128-dy]; row 128 = unconditional min. */
    int oct    = tid & 7;
    int colsel = (tid >> 3) & 1;
    int dy     = (tid >> 4) + 1;
    int d2     = dy * dy;
    const uint2* lst = colsel ? s_rec1 : s_rec0;
    int nc = colsel ? nc1 : nc0;

    float mv = 1.0f, mvu = 1.0f;
    #pragma unroll 4
    for (int e = oct; e < nc; e += 8) {
        uint2 rr = lst[e];
        float d = __uint_as_float(rr.y);
        mvu = fminf(mvu, d);
        if (d2 <= (int)rr.x) mv = fminf(mv, d);
    }
    #pragma unroll
    for (int off = 1; off < 8; off <<= 1) {
        mv  = fminf(mv,  __shfl_xor_sync(0xffffffffu, mv,  off));
        mvu = fminf(mvu, __shfl_xor_sync(0xffffffffu, mvu, off));
    }
    if (oct == 0) {
        int col = c0 + colsel;
        out[(128 + dy) * IMG + col] = mv;
        out[(128 - dy) * IMG + col] = mv;
        if (dy == 1) out[128 * IMG + col] = mvu;
    }
}

extern "C" void kernel_launch(void* const* d_in, const int* in_sizes, int n_in,
                              void* d_out, int out_size) {
    const float* agent  = (const float*)d_in[0];
    const float* goal   = (const float*)d_in[1];
    const float* others = (const float*)d_in[2];
    const float* obs    = (const float*)d_in[3];
    float* out          = (float*)d_out;

    render_kernel<<<NB, PT>>>(agent, goal, others, obs, out);
}

// round 17
// speedup vs baseline: 1.2657x; 1.2657x over previous
#include <cuda_runtime.h>
#include <math.h>

#define IMG 256
#define MAX_R 64
#define N_AG 2047
#define N_ENT 4095
#define FOVH 0.7853981633974483f   /* rounds to float 0x3F490FDB > pi/4 */
#define PT 1024
#define NB 128                     /* 2 cols per block, single wave */

__global__ __launch_bounds__(PT)
void render_kernel(const float* __restrict__ agent,
                   const float* __restrict__ goal,
                   const float* __restrict__ others,
                   const float* __restrict__ obs,
                   float* __restrict__ out) {
    __shared__ unsigned short s_surv[32][128];  /* per-warp survivor ids */
    __shared__ uint2 s_rec0[2048];              /* col c0: {rem, depth} */
    __shared__ uint2 s_rec1[2048];              /* col c1 */
    __shared__ int   s_wcnt[32];
    __shared__ int   s_wbase[32];
    __shared__ int   s_cwc[32];
    __shared__ int   s_round;                   /* packed round total */
    __shared__ int   s_maxw;

    int tid  = threadIdx.x;
    int warp = tid >> 5;
    unsigned lane = tid & 31;
    unsigned pre = (1u << lane) - 1u;
    int c0 = blockIdx.x * 2;

    /* camera basis */
    float ax = agent[0], ay = agent[1];
    float vx = goal[0] - ax, vy = goal[1] - ay;
    float inv = 1.0f / (sqrtf(vx * vx + vy * vy) + 1e-8f);
    vx *= inv; vy *= inv;
    float cb = vy, sb = vx;

    /* ---- cheap pass: FFMA-only conservative filter (no MUFU) ---- */
    int wcnt = 0;
    #pragma unroll
    for (int k = 0; k < 4; k++) {
        int e = (warp << 7) + (k << 5) + (int)lane;
        float ex, ey;
        if (e < N_AG) {
            float2 p = __ldg((const float2*)(others + 2 * e));
            ex = p.x; ey = p.y;
        } else if (e < N_ENT) {
            int o = e - N_AG;
            ex = __ldg(obs + 3 * o);
            ey = __ldg(obs + 3 * o + 1);
        } else {
            ex = 1e9f; ey = -1e9f;
        }
        float rx = ex - ax, ry = ey - ay;
        float camx =  cb * rx + sb * ry;
        float camy = -sb * rx + cb * ry;
        float s2 = camx * camx + camy * camy;
        /* superset of (camy>=0 && |atan2(camx,camy)|<=FOVH && dist<=3) */
        bool surv = (camy >= 0.0f) &&
                    (fabsf(camx) <= camy * 1.000002f) &&
                    (s2 <= 9.000002f);
        unsigned m = __ballot_sync(0xffffffffu, surv);
        if (surv) s_surv[warp][wcnt + __popc(m & pre)] = (unsigned short)e;
        wcnt += __popc(m);
    }
    if (lane == 0) s_cwc[warp] = wcnt;

    /* background rows (rows 0..63, 193..255; 2 cols) — independent */
    if (tid < 254) {
        int r = tid >> 1;
        int row = (r < 64) ? r : r + 129;
        out[row * IMG + c0 + (tid & 1)] = 1.0f;
    }
    __syncthreads();

    if (warp == 0) {                 /* block max of cheap counts */
        int v = s_cwc[lane];
        #pragma unroll
        for (int off = 16; off; off >>= 1)
            v = max(v, __shfl_xor_sync(0xffffffffu, v, off));
        if (lane == 0) s_maxw = v;
    }
    __syncthreads();
    int rounds = (s_maxw + 31) >> 5;
    int tot = 0;                     /* packed running totals (cnt0<<16|cnt1) */

    /* ---- heavy pass: exact transform only for survivors ---- */
    for (int j = 0; j < rounds; j++) {
        int i = (j << 5) + (int)lane;
        int rem0 = -1, rem1 = -1; unsigned dep = 0u;
        if (i < wcnt) {
            int e = s_surv[warp][i];
            float ex, ey, r, h;
            if (e < N_AG) {
                float2 p = __ldg((const float2*)(others + 2 * e));
                ex = p.x; ey = p.y; r = 0.05f; h = 0.2f;
            } else {
                int o = e - N_AG;
                ex = __ldg(obs + 3 * o);
                ey = __ldg(obs + 3 * o + 1);
                r  = __ldg(obs + 3 * o + 2);
                h  = 0.5f;
            }
            float rx = ex - ax, ry = ey - ay;
            float camx =  cb * rx + sb * ry;
            float camy = -sb * rx + cb * ry;
            float dist = sqrtf(camx * camx + camy * camy);
            float angle = atan2f(camx, camy);
            if ((camy >= 0.0f) && (dist <= 3.0f) && (fabsf(angle) <= FOVH)) {
                float pixel_x = angle / FOVH * 0.5f;
                int pxi = (int)floorf((pixel_x + 0.5f) * (float)IMG);
                int pr  = (int)floorf(r / (dist + 1e-8f) * (float)IMG * 0.5f);
                pr = min(max(pr, 1), MAX_R);
                int pr2 = pr * pr;
                float depth = fminf(dist / 3.0f, 1.0f) * (1.0f - h * 0.3f);
                depth = fmaxf(depth, 0.0f);
                int dx0 = c0 - pxi;
                int dx1 = dx0 + 1;
                rem0 = pr2 - dx0 * dx0;
                rem1 = pr2 - dx1 * dx1;
                dep  = __float_as_uint(depth);
            }
        }
        unsigned m0 = __ballot_sync(0xffffffffu, rem0 >= 0);
        unsigned m1 = __ballot_sync(0xffffffffu, rem1 >= 0);
        if (lane == 0) s_wcnt[warp] = (__popc(m0) << 16) | __popc(m1);
        __syncthreads();

        if (warp == 0) {             /* packed exclusive scan (carry-free) */
            int v = s_wcnt[lane];
            int incl = v;
            #pragma unroll
            for (int off = 1; off < 32; off <<= 1) {
                int t = __shfl_up_sync(0xffffffffu, incl, off);
                if ((int)lane >= off) incl += t;
            }
            s_wbase[lane] = incl - v;
            if (lane == 31) s_round = incl;
        }
        __syncthreads();

        int bp = tot + s_wbase[warp];
        int b0 = bp >> 16, b1 = bp & 0xffff;
        if (rem0 >= 0) s_rec0[b0 + __popc(m0 & pre)] = make_uint2((unsigned)rem0, dep);
        if (rem1 >= 0) s_rec1[b1 + __popc(m1 & pre)] = make_uint2((unsigned)rem1, dep);
        tot += s_round;
    }
    __syncthreads();
    int nc0 = tot >> 16;
    int nc1 = tot & 0xffff;

    /* ---- phase B: tid = [dyidx:6][colsel:1][oct:3]; dy in 1..64.
       Symmetry: out[128+dy] == out[128-dy]; row 128 = unconditional min. */
    int oct    = tid & 7;
    int colsel = (tid >> 3) & 1;
    int dy     = (tid >> 4) + 1;
    int d2     = dy * dy;
    const uint2* lst = colsel ? s_rec1 : s_rec0;
    int nc = colsel ? nc1 : nc0;

    float mv = 1.0f, mvu = 1.0f;
    #pragma unroll 4
    for (int e = oct; e < nc; e += 8) {
        uint2 rr = lst[e];
        float d = __uint_as_float(rr.y);
        mvu = fminf(mvu, d);
        if (d2 <= (int)rr.x) mv = fminf(mv, d);
    }
    #pragma unroll
    for (int off = 1; off < 8; off <<= 1) {
        mv  = fminf(mv,  __shfl_xor_sync(0xffffffffu, mv,  off));
        mvu = fminf(mvu, __shfl_xor_sync(0xffffffffu, mvu, off));
    }
    if (oct == 0) {
        int col = c0 + colsel;
        out[(128 + dy) * IMG + col] = mv;
        out[(128 - dy) * IMG + col] = mv;
        if (dy == 1) out[128 * IMG + col] = mvu;
    }
}

extern "C" void kernel_launch(void* const* d_in, const int* in_sizes, int n_in,
                              void* d_out, int out_size) {
    const float* agent  = (const float*)d_in[0];
    const float* goal   = (const float*)d_in[1];
    const float* others = (const float*)d_in[2];
    const float* obs    = (const float*)d_in[3];
    float* out          = (float*)d_out;

    render_kernel<<<NB, PT>>>(agent, goal, others, obs, out);
}